// round 1
// baseline (speedup 1.0000x reference)
#include <cuda_runtime.h>
#include <math.h>

#define NTOK 4096
#define EMB  1024
#define HID  2816
#define NE   8

#define BM 64
#define BN 64
#define BK 16

// ---------------- device scratch (static __device__: allowed, no allocs) ----
__device__ int   g_cnt[NE];
__device__ int   g_off[NE];
__device__ int   g_tok[NE][NTOK];
__device__ float g_gate[NE][NTOK];
// compact H buffer: exactly 2*NTOK rows total (every token -> 2 experts)
__device__ float g_h[(size_t)2 * NTOK * HID];

// ---------------- reset per-launch state --------------------------------
__global__ void k_reset() {
    if (threadIdx.x < NE) g_cnt[threadIdx.x] = 0;
}

// ---------------- router: scores, top-2, softmax, build expert lists -----
__global__ void k_router(const float* __restrict__ x, const float* __restrict__ wr) {
    int t    = blockIdx.x * (blockDim.x >> 5) + (threadIdx.x >> 5);
    int lane = threadIdx.x & 31;
    if (t >= NTOK) return;
    const float* xr = x + (size_t)t * EMB;

    float acc[NE];
#pragma unroll
    for (int e = 0; e < NE; e++) acc[e] = 0.f;
    for (int i = lane; i < EMB; i += 32) {
        float xv = xr[i];
#pragma unroll
        for (int e = 0; e < NE; e++) acc[e] += xv * wr[i * NE + e];
    }
#pragma unroll
    for (int e = 0; e < NE; e++)
#pragma unroll
        for (int o = 16; o > 0; o >>= 1)
            acc[e] += __shfl_xor_sync(0xffffffffu, acc[e], o);

    if (lane == 0) {
        int i0 = 0; float v0 = acc[0];
#pragma unroll
        for (int e = 1; e < NE; e++) if (acc[e] > v0) { v0 = acc[e]; i0 = e; }
        int i1 = -1; float v1 = -3.4e38f;
#pragma unroll
        for (int e = 0; e < NE; e++) if (e != i0 && acc[e] > v1) { v1 = acc[e]; i1 = e; }

        // softmax over the two top scores (v0 >= v1)
        float z  = expf(v1 - v0);
        float p0 = 1.f / (1.f + z);
        float p1 = z  / (1.f + z);

        int s0 = atomicAdd(&g_cnt[i0], 1);
        g_tok[i0][s0]  = t;  g_gate[i0][s0] = p0;
        int s1 = atomicAdd(&g_cnt[i1], 1);
        g_tok[i1][s1]  = t;  g_gate[i1][s1] = p1;
    }
}

__global__ void k_prefix() {
    if (threadIdx.x == 0) {
        int o = 0;
        for (int e = 0; e < NE; e++) { g_off[e] = o; o += g_cnt[e]; }
    }
}

// ---------------- GEMM1: H = silu(X@W1) * (X@W3), per expert -------------
__global__ void __launch_bounds__(256)
k_gemm1(const float* __restrict__ x,
        const float* __restrict__ w1,
        const float* __restrict__ w3) {
    int e  = blockIdx.z;
    int ne = g_cnt[e];
    int m0 = blockIdx.y * BM;
    if (m0 >= ne) return;
    int n0 = blockIdx.x * BN;

    __shared__ float sx [BK][BM + 1];
    __shared__ float sw1[BK][BN];
    __shared__ float sw3[BK][BN];

    int tid = threadIdx.x;
    int tx = tid & 15, ty = tid >> 4;

    // x-tile load mapping: kx = tid&15 (contiguous k per row), 4 rows/thread
    int kx = tid & 15;
    int mxBase = tid >> 4;            // 0..15
    int tokRow[4];
#pragma unroll
    for (int mm = 0; mm < 4; mm++) {
        int gm = m0 + mxBase + mm * 16;
        tokRow[mm] = (gm < ne) ? g_tok[e][gm] : -1;
    }

    // w-tile load mapping: nw contiguous for coalescing
    int nw = tid & 63;
    int kwBase = tid >> 6;            // 0..3
    const float* w1base = w1 + (size_t)e * EMB * HID + n0 + nw;
    const float* w3base = w3 + (size_t)e * EMB * HID + n0 + nw;

    float acc1[4][4], acc3[4][4];
#pragma unroll
    for (int i = 0; i < 4; i++)
#pragma unroll
        for (int j = 0; j < 4; j++) { acc1[i][j] = 0.f; acc3[i][j] = 0.f; }

    for (int k0 = 0; k0 < EMB; k0 += BK) {
#pragma unroll
        for (int mm = 0; mm < 4; mm++) {
            int m = mxBase + mm * 16;
            sx[kx][m] = (tokRow[mm] >= 0)
                      ? x[(size_t)tokRow[mm] * EMB + k0 + kx] : 0.f;
        }
#pragma unroll
        for (int kk = 0; kk < 4; kk++) {
            int k = kwBase + kk * 4;
            sw1[k][nw] = w1base[(size_t)(k0 + k) * HID];
            sw3[k][nw] = w3base[(size_t)(k0 + k) * HID];
        }
        __syncthreads();

#pragma unroll
        for (int k = 0; k < BK; k++) {
            float a[4], b1v[4], b3v[4];
#pragma unroll
            for (int i = 0; i < 4; i++) a[i] = sx[k][ty * 4 + i];
#pragma unroll
            for (int j = 0; j < 4; j++) { b1v[j] = sw1[k][tx * 4 + j];
                                          b3v[j] = sw3[k][tx * 4 + j]; }
#pragma unroll
            for (int i = 0; i < 4; i++)
#pragma unroll
                for (int j = 0; j < 4; j++) {
                    acc1[i][j] += a[i] * b1v[j];
                    acc3[i][j] += a[i] * b3v[j];
                }
        }
        __syncthreads();
    }

    int ho = g_off[e];
#pragma unroll
    for (int i = 0; i < 4; i++) {
        int gm = m0 + ty * 4 + i;
        if (gm >= ne) continue;
        float* hrow = g_h + (size_t)(ho + gm) * HID + n0;
#pragma unroll
        for (int j = 0; j < 4; j++) {
            float zv = acc1[i][j];
            float s  = zv / (1.f + expf(-zv));     // silu
            hrow[tx * 4 + j] = s * acc3[i][j];
        }
    }
}

// ---------------- GEMM2: Y = H @ W2, scatter out += gate * Y -------------
__global__ void __launch_bounds__(256)
k_gemm2(const float* __restrict__ w2, float* __restrict__ out) {
    int e  = blockIdx.z;
    int ne = g_cnt[e];
    int m0 = blockIdx.y * BM;
    if (m0 >= ne) return;
    int n0 = blockIdx.x * BN;

    __shared__ float sa[BK][BM + 1];
    __shared__ float sb[BK][BN];

    int tid = threadIdx.x;
    int tx = tid & 15, ty = tid >> 4;

    int ka = tid & 15;
    int maBase = tid >> 4;
    int ho = g_off[e];

    int nw = tid & 63;
    int kwBase = tid >> 6;
    const float* w2base = w2 + (size_t)e * HID * EMB + n0 + nw;

    float acc[4][4];
#pragma unroll
    for (int i = 0; i < 4; i++)
#pragma unroll
        for (int j = 0; j < 4; j++) acc[i][j] = 0.f;

    for (int k0 = 0; k0 < HID; k0 += BK) {
#pragma unroll
        for (int mm = 0; mm < 4; mm++) {
            int m  = maBase + mm * 16;
            int gm = m0 + m;
            sa[ka][m] = (gm < ne)
                      ? g_h[(size_t)(ho + gm) * HID + k0 + ka] : 0.f;
        }
#pragma unroll
        for (int kk = 0; kk < 4; kk++) {
            int k = kwBase + kk * 4;
            sb[k][nw] = w2base[(size_t)(k0 + k) * EMB];
        }
        __syncthreads();

#pragma unroll
        for (int k = 0; k < BK; k++) {
            float a[4], b[4];
#pragma unroll
            for (int i = 0; i < 4; i++) a[i] = sa[k][ty * 4 + i];
#pragma unroll
            for (int j = 0; j < 4; j++) b[j] = sb[k][tx * 4 + j];
#pragma unroll
            for (int i = 0; i < 4; i++)
#pragma unroll
                for (int j = 0; j < 4; j++)
                    acc[i][j] += a[i] * b[j];
        }
        __syncthreads();
    }

#pragma unroll
    for (int i = 0; i < 4; i++) {
        int gm = m0 + ty * 4 + i;
        if (gm >= ne) continue;
        int   tok = g_tok[e][gm];
        float gt  = g_gate[e][gm];
        float* orow = out + (size_t)tok * EMB + n0;
#pragma unroll
        for (int j = 0; j < 4; j++)
            atomicAdd(&orow[tx * 4 + j], gt * acc[i][j]);
    }
}

// ---------------- launcher -----------------------------------------------
extern "C" void kernel_launch(void* const* d_in, const int* in_sizes, int n_in,
                              void* d_out, int out_size) {
    const float* x  = (const float*)d_in[0];
    const float* wr = (const float*)d_in[1];
    const float* w1 = (const float*)d_in[2];
    const float* w3 = (const float*)d_in[3];
    const float* w2 = (const float*)d_in[4];
    float* out = (float*)d_out;

    cudaMemsetAsync(out, 0, (size_t)out_size * sizeof(float));

    k_reset<<<1, 32>>>();
    k_router<<<NTOK / 8, 256>>>(x, wr);
    k_prefix<<<1, 1>>>();

    dim3 g1(HID / BN, NTOK / BM, NE);   // 44 x 64 x 8
    k_gemm1<<<g1, 256>>>(x, w1, w3);

    dim3 g2(EMB / BN, NTOK / BM, NE);   // 16 x 64 x 8
    k_gemm2<<<g2, 256>>>(w2, out);
}

// round 3
// speedup vs baseline: 3.1868x; 3.1868x over previous
#include <cuda_runtime.h>
#include <cstdint>
#include <math.h>

#define NTOK 4096
#define EMB  1024
#define HID  2816
#define NE   8
#define MAXPAD 9216

// ===================== device scratch =====================
__device__ int   g_cnt[NE];
__device__ int   g_offp[NE];
__device__ int   g_tok[NE][NTOK];
__device__ float g_gate[NE][NTOK];
__device__ int   g_texp[NTOK][2];
__device__ int   g_trow[NTOK][2];

__device__ float g_xp[(size_t)MAXPAD * EMB];      // gathered tokens, tf32-rounded
__device__ float g_h [(size_t)MAXPAD * HID];      // SwiGLU intermediate, tf32-rounded
__device__ float g_y [(size_t)MAXPAD * EMB];      // gated expert outputs
__device__ float g_w1r[(size_t)NE * EMB * HID];   // tf32-rounded weights (same layout)
__device__ float g_w3r[(size_t)NE * EMB * HID];
__device__ float g_w2r[(size_t)NE * HID * EMB];

// ===================== helpers =====================
__device__ __forceinline__ uint32_t tf32r(float f) {
    uint32_t u;
    asm("cvt.rna.tf32.f32 %0, %1;" : "=r"(u) : "f"(f));
    return u;
}
__device__ __forceinline__ void mma8(float* c, const uint32_t* a, const uint32_t* b) {
    asm volatile("mma.sync.aligned.m16n8k8.row.col.f32.tf32.tf32.f32 "
        "{%0,%1,%2,%3}, {%4,%5,%6,%7}, {%8,%9}, {%0,%1,%2,%3};"
        : "+f"(c[0]), "+f"(c[1]), "+f"(c[2]), "+f"(c[3])
        : "r"(a[0]), "r"(a[1]), "r"(a[2]), "r"(a[3]), "r"(b[0]), "r"(b[1]));
}
__device__ __forceinline__ uint32_t s2u(const void* p) {
    uint32_t a;
    asm("{ .reg .u64 t; cvta.to.shared.u64 t, %1; cvt.u32.u64 %0, t; }" : "=r"(a) : "l"(p));
    return a;
}
__device__ __forceinline__ void cp16(uint32_t dst, const void* src) {
    asm volatile("cp.async.cg.shared.global [%0], [%1], 16;" :: "r"(dst), "l"(src));
}
#define CP_COMMIT() asm volatile("cp.async.commit_group;" ::: "memory")

// ===================== small kernels =====================
__global__ void k_reset() { if (threadIdx.x < NE) g_cnt[threadIdx.x] = 0; }

__global__ void k_round(const float4* __restrict__ src, float4* __restrict__ dst) {
    size_t i = (size_t)blockIdx.x * blockDim.x + threadIdx.x;
    float4 v = src[i];
    v.x = __uint_as_float(tf32r(v.x));
    v.y = __uint_as_float(tf32r(v.y));
    v.z = __uint_as_float(tf32r(v.z));
    v.w = __uint_as_float(tf32r(v.w));
    dst[i] = v;
}

__global__ void k_router(const float* __restrict__ x, const float* __restrict__ wr) {
    int t    = blockIdx.x * (blockDim.x >> 5) + (threadIdx.x >> 5);
    int lane = threadIdx.x & 31;
    if (t >= NTOK) return;
    const float* xr = x + (size_t)t * EMB;
    float acc[NE];
#pragma unroll
    for (int e = 0; e < NE; e++) acc[e] = 0.f;
    for (int i = lane; i < EMB; i += 32) {
        float xv = xr[i];
#pragma unroll
        for (int e = 0; e < NE; e++) acc[e] += xv * wr[i * NE + e];
    }
#pragma unroll
    for (int e = 0; e < NE; e++)
#pragma unroll
        for (int o = 16; o > 0; o >>= 1) acc[e] += __shfl_xor_sync(0xffffffffu, acc[e], o);
    if (lane == 0) {
        int i0 = 0; float v0 = acc[0];
#pragma unroll
        for (int e = 1; e < NE; e++) if (acc[e] > v0) { v0 = acc[e]; i0 = e; }
        int i1 = -1; float v1 = -3.4e38f;
#pragma unroll
        for (int e = 0; e < NE; e++) if (e != i0 && acc[e] > v1) { v1 = acc[e]; i1 = e; }
        float z  = expf(v1 - v0);
        float p0 = 1.f / (1.f + z);
        float p1 = z  / (1.f + z);
        int s0 = atomicAdd(&g_cnt[i0], 1);
        g_tok[i0][s0] = t; g_gate[i0][s0] = p0; g_texp[t][0] = i0; g_trow[t][0] = s0;
        int s1 = atomicAdd(&g_cnt[i1], 1);
        g_tok[i1][s1] = t; g_gate[i1][s1] = p1; g_texp[t][1] = i1; g_trow[t][1] = s1;
    }
}

__global__ void k_prefix() {
    if (threadIdx.x == 0) {
        int op = 0;
        for (int e = 0; e < NE; e++) { g_offp[e] = op; op += (g_cnt[e] + 127) & ~127; }
    }
}

__global__ void k_gather(const float* __restrict__ x) {
    int e = blockIdx.y; int cnt = g_cnt[e];
    int m0 = blockIdx.x * 128;
    if (m0 >= cnt) return;
    int tid = threadIdx.x;
    float* dst = g_xp + (size_t)(g_offp[e] + m0) * EMB;
    for (int id = tid; id < 128 * 256; id += 256) {
        int r = id >> 8, j = id & 255;
        int gm = m0 + r;
        float4 v = make_float4(0.f, 0.f, 0.f, 0.f);
        if (gm < cnt) {
            v = ((const float4*)(x + (size_t)g_tok[e][gm] * EMB))[j];
            v.x = __uint_as_float(tf32r(v.x));
            v.y = __uint_as_float(tf32r(v.y));
            v.z = __uint_as_float(tf32r(v.z));
            v.w = __uint_as_float(tf32r(v.w));
        }
        ((float4*)(dst + (size_t)r * EMB))[j] = v;
    }
}

// ===================== GEMM1: H = silu(X@W1)*(X@W3) =====================
// tiles 128x128x32, 8 warps (2x4), warp tile 64x32, m16n8k8 tf32
#define A_F   4608            // 128*36 floats (pad 4)
#define B_F   4224            // 32*132 floats (pad 4)
#define ST1F  (A_F + 2*B_F)   // 13056 floats
#define STG1  3
#define KB1   (EMB/32)

__global__ void __launch_bounds__(256, 1) k_mma1() {
    extern __shared__ float sm[];
    int e = blockIdx.z;
    int cnt = g_cnt[e];
    int m0 = blockIdx.y * 128;
    if (m0 >= cnt) return;
    int n0 = blockIdx.x * 128;
    int tid = threadIdx.x, lane = tid & 31, wid = tid >> 5;
    int wm = wid >> 2, wn = wid & 3;
    int grp = lane >> 2, q = lane & 3;
    uint32_t sbase = s2u(sm);
    int ho = g_offp[e] + m0;

    const float* gA  = g_xp  + (size_t)ho * EMB;
    const float* gB1 = g_w1r + (size_t)e * EMB * HID + n0;
    const float* gB3 = g_w3r + (size_t)e * EMB * HID + n0;

    auto load_stage = [&](int kb, int s) {
        uint32_t st = sbase + (uint32_t)s * ST1F * 4;
        int k0 = kb * 32;
#pragma unroll
        for (int it = 0; it < 4; it++) {
            int id = it * 256 + tid;
            int r = id >> 3, c = id & 7;
            cp16(st + (uint32_t)(r * 36 + c * 4) * 4, gA + (size_t)r * EMB + k0 + c * 4);
        }
#pragma unroll
        for (int it = 0; it < 4; it++) {
            int id = it * 256 + tid;
            int k = id >> 5, c = id & 31;
            uint32_t so = (uint32_t)(k * 132 + c * 4) * 4;
            cp16(st + A_F * 4 + so,         gB1 + (size_t)(k0 + k) * HID + c * 4);
            cp16(st + (A_F + B_F) * 4 + so, gB3 + (size_t)(k0 + k) * HID + c * 4);
        }
        CP_COMMIT();
    };

    float accZ[4][4][4], accG[4][4][4];
#pragma unroll
    for (int i = 0; i < 4; i++)
#pragma unroll
        for (int j = 0; j < 4; j++)
#pragma unroll
            for (int r = 0; r < 4; r++) { accZ[i][j][r] = 0.f; accG[i][j][r] = 0.f; }

    load_stage(0, 0);
    load_stage(1, 1);

    for (int kb = 0; kb < KB1; kb++) {
        asm volatile("cp.async.wait_group 1;" ::: "memory");
        __syncthreads();
        const float* st  = sm + (kb % STG1) * ST1F;
        const float* sA  = st;
        const float* sB1 = st + A_F;
        const float* sB3 = st + A_F + B_F;
#pragma unroll
        for (int ks = 0; ks < 4; ks++) {
            int kk = ks * 8;
            uint32_t a[4][4];
#pragma unroll
            for (int i = 0; i < 4; i++) {
                int r = wm * 64 + i * 16 + grp;
                a[i][0] = __float_as_uint(sA[r * 36 + kk + q]);
                a[i][1] = __float_as_uint(sA[(r + 8) * 36 + kk + q]);
                a[i][2] = __float_as_uint(sA[r * 36 + kk + 4 + q]);
                a[i][3] = __float_as_uint(sA[(r + 8) * 36 + kk + 4 + q]);
            }
            uint32_t b1[4][2], b3[4][2];
#pragma unroll
            for (int j = 0; j < 4; j++) {
                int c = wn * 32 + j * 8 + grp;
                b1[j][0] = __float_as_uint(sB1[(kk + q) * 132 + c]);
                b1[j][1] = __float_as_uint(sB1[(kk + 4 + q) * 132 + c]);
                b3[j][0] = __float_as_uint(sB3[(kk + q) * 132 + c]);
                b3[j][1] = __float_as_uint(sB3[(kk + 4 + q) * 132 + c]);
            }
#pragma unroll
            for (int i = 0; i < 4; i++)
#pragma unroll
                for (int j = 0; j < 4; j++) {
                    mma8(accZ[i][j], a[i], b1[j]);
                    mma8(accG[i][j], a[i], b3[j]);
                }
        }
        if (kb + 2 < KB1) load_stage(kb + 2, (kb + 2) % STG1);
        else CP_COMMIT();
    }

    // epilogue: SwiGLU, round to tf32, store
    float* gH = g_h + (size_t)ho * HID + n0;
#pragma unroll
    for (int i = 0; i < 4; i++) {
        int r = wm * 64 + i * 16 + grp;
#pragma unroll
        for (int j = 0; j < 4; j++) {
            int c = wn * 32 + j * 8 + 2 * q;
            float h[4];
#pragma unroll
            for (int t2 = 0; t2 < 4; t2++) {
                float z = accZ[i][j][t2];
                float g = accG[i][j][t2];
                float s = z / (1.f + __expf(-z));
                h[t2] = __uint_as_float(tf32r(s * g));
            }
            *(float2*)(gH + (size_t)r * HID + c)       = make_float2(h[0], h[1]);
            *(float2*)(gH + (size_t)(r + 8) * HID + c) = make_float2(h[2], h[3]);
        }
    }
}

// ===================== GEMM2: Y = gate * (H @ W2) =====================
#define ST2F  (A_F + B_F)     // 8832 floats
#define STG2  4
#define KB2   (HID/32)

__global__ void __launch_bounds__(256, 1) k_mma2() {
    extern __shared__ float sm[];
    int e = blockIdx.z;
    int cnt = g_cnt[e];
    int m0 = blockIdx.y * 128;
    if (m0 >= cnt) return;
    int n0 = blockIdx.x * 128;
    int tid = threadIdx.x, lane = tid & 31, wid = tid >> 5;
    int wm = wid >> 2, wn = wid & 3;
    int grp = lane >> 2, q = lane & 3;
    uint32_t sbase = s2u(sm);
    int ho = g_offp[e] + m0;

    const float* gA = g_h   + (size_t)ho * HID;
    const float* gB = g_w2r + (size_t)e * HID * EMB + n0;

    auto load_stage = [&](int kb, int s) {
        uint32_t st = sbase + (uint32_t)s * ST2F * 4;
        int k0 = kb * 32;
#pragma unroll
        for (int it = 0; it < 4; it++) {
            int id = it * 256 + tid;
            int r = id >> 3, c = id & 7;
            cp16(st + (uint32_t)(r * 36 + c * 4) * 4, gA + (size_t)r * HID + k0 + c * 4);
        }
#pragma unroll
        for (int it = 0; it < 4; it++) {
            int id = it * 256 + tid;
            int k = id >> 5, c = id & 31;
            cp16(st + A_F * 4 + (uint32_t)(k * 132 + c * 4) * 4,
                 gB + (size_t)(k0 + k) * EMB + c * 4);
        }
        CP_COMMIT();
    };

    float acc[4][4][4];
#pragma unroll
    for (int i = 0; i < 4; i++)
#pragma unroll
        for (int j = 0; j < 4; j++)
#pragma unroll
            for (int r = 0; r < 4; r++) acc[i][j][r] = 0.f;

    load_stage(0, 0);
    load_stage(1, 1);
    load_stage(2, 2);

    for (int kb = 0; kb < KB2; kb++) {
        asm volatile("cp.async.wait_group 2;" ::: "memory");
        __syncthreads();
        const float* st = sm + (kb % STG2) * ST2F;
        const float* sA = st;
        const float* sB = st + A_F;
#pragma unroll
        for (int ks = 0; ks < 4; ks++) {
            int kk = ks * 8;
            uint32_t a[4][4];
#pragma unroll
            for (int i = 0; i < 4; i++) {
                int r = wm * 64 + i * 16 + grp;
                a[i][0] = __float_as_uint(sA[r * 36 + kk + q]);
                a[i][1] = __float_as_uint(sA[(r + 8) * 36 + kk + q]);
                a[i][2] = __float_as_uint(sA[r * 36 + kk + 4 + q]);
                a[i][3] = __float_as_uint(sA[(r + 8) * 36 + kk + 4 + q]);
            }
            uint32_t b[4][2];
#pragma unroll
            for (int j = 0; j < 4; j++) {
                int c = wn * 32 + j * 8 + grp;
                b[j][0] = __float_as_uint(sB[(kk + q) * 132 + c]);
                b[j][1] = __float_as_uint(sB[(kk + 4 + q) * 132 + c]);
            }
#pragma unroll
            for (int i = 0; i < 4; i++)
#pragma unroll
                for (int j = 0; j < 4; j++)
                    mma8(acc[i][j], a[i], b[j]);
        }
        if (kb + 3 < KB2) load_stage(kb + 3, (kb + 3) % STG2);
        else CP_COMMIT();
    }

    float* gY = g_y + (size_t)ho * EMB + n0;
#pragma unroll
    for (int i = 0; i < 4; i++) {
        int r = wm * 64 + i * 16 + grp;
        bool act0 = (m0 + r) < cnt;
        bool act1 = (m0 + r + 8) < cnt;
        float gt0 = act0 ? g_gate[e][m0 + r] : 0.f;
        float gt1 = act1 ? g_gate[e][m0 + r + 8] : 0.f;
#pragma unroll
        for (int j = 0; j < 4; j++) {
            int c = wn * 32 + j * 8 + 2 * q;
            if (act0)
                *(float2*)(gY + (size_t)r * EMB + c) =
                    make_float2(gt0 * acc[i][j][0], gt0 * acc[i][j][1]);
            if (act1)
                *(float2*)(gY + (size_t)(r + 8) * EMB + c) =
                    make_float2(gt1 * acc[i][j][2], gt1 * acc[i][j][3]);
        }
    }
}

// ===================== combine =====================
__global__ void k_combine(float* __restrict__ out) {
    int t = blockIdx.x;
    int e0 = g_texp[t][0], e1 = g_texp[t][1];
    const float4* y0 = (const float4*)(g_y + (size_t)(g_offp[e0] + g_trow[t][0]) * EMB);
    const float4* y1 = (const float4*)(g_y + (size_t)(g_offp[e1] + g_trow[t][1]) * EMB);
    float4 a = y0[threadIdx.x], b = y1[threadIdx.x];
    ((float4*)(out + (size_t)t * EMB))[threadIdx.x] =
        make_float4(a.x + b.x, a.y + b.y, a.z + b.z, a.w + b.w);
}

// ===================== launcher =====================
extern "C" void kernel_launch(void* const* d_in, const int* in_sizes, int n_in,
                              void* d_out, int out_size) {
    const float* x  = (const float*)d_in[0];
    const float* wr = (const float*)d_in[1];
    const float* w1 = (const float*)d_in[2];
    const float* w3 = (const float*)d_in[3];
    const float* w2 = (const float*)d_in[4];
    float* out = (float*)d_out;

    const int SM1 = STG1 * ST1F * 4;   // 156672
    const int SM2 = STG2 * ST2F * 4;   // 141312
    cudaFuncSetAttribute(k_mma1, cudaFuncAttributeMaxDynamicSharedMemorySize, SM1);
    cudaFuncSetAttribute(k_mma2, cudaFuncAttributeMaxDynamicSharedMemorySize, SM2);

    const int N4 = NE * EMB * HID / 4;           // 5767168
    float* w1r; cudaGetSymbolAddress((void**)&w1r, g_w1r);
    float* w3r; cudaGetSymbolAddress((void**)&w3r, g_w3r);
    float* w2r; cudaGetSymbolAddress((void**)&w2r, g_w2r);
    k_round<<<N4 / 256, 256>>>((const float4*)w1, (float4*)w1r);
    k_round<<<N4 / 256, 256>>>((const float4*)w3, (float4*)w3r);
    k_round<<<N4 / 256, 256>>>((const float4*)w2, (float4*)w2r);

    k_reset<<<1, 32>>>();
    k_router<<<NTOK / 8, 256>>>(x, wr);
    k_prefix<<<1, 1>>>();
    k_gather<<<dim3(NTOK / 128, NE), 256>>>(x);

    k_mma1<<<dim3(HID / 128, NTOK / 128, NE), 256, SM1>>>();
    k_mma2<<<dim3(EMB / 128, NTOK / 128, NE), 256, SM2>>>();
    k_combine<<<NTOK, 256>>>(out);
}